// round 4
// baseline (speedup 1.0000x reference)
#include <cuda_runtime.h>
#include <math.h>

typedef unsigned long long ull;
typedef unsigned int uint;

#define TT 8192
#define HH 512

// ---------------- scratch: packed {flag(hi32), h_bits(lo32)} mailboxes ----------------
__device__ ull g_p1[(TT + 1) * HH];
__device__ ull g_p2[(TT + 1) * HH];

// ---------------- primitives ----------------
__device__ __forceinline__ ull ld_rlx(const ull* p) {
    ull v;
    asm volatile("ld.relaxed.gpu.global.u64 %0, [%1];" : "=l"(v) : "l"(p) : "memory");
    return v;
}
__device__ __forceinline__ void st_rlx(ull* p, ull v) {
    asm volatile("st.relaxed.gpu.global.u64 [%0], %1;" :: "l"(p), "l"(v) : "memory");
}
__device__ __forceinline__ ull packhf(unsigned flag, float h) {
    return ((ull)flag << 32) | (ull)__float_as_uint(h);
}
__device__ __forceinline__ float lo_f(ull v) { return __uint_as_float((unsigned)v); }
__device__ __forceinline__ unsigned hi_u(ull v) { return (unsigned)(v >> 32); }

__device__ __forceinline__ void ffma2(ull& acc, ull w, ull v) {
    asm("fma.rn.f32x2 %0, %1, %2, %0;" : "+l"(acc) : "l"(w), "l"(v));
}
__device__ __forceinline__ ull addf2(ull a, ull b) {
    ull r;
    asm("add.rn.f32x2 %0, %1, %2;" : "=l"(r) : "l"(a), "l"(b));
    return r;
}
__device__ __forceinline__ ull packf2(float a, float b) {
    ull r;
    asm("mov.b64 %0, {%1,%2};" : "=l"(r) : "f"(a), "f"(b));
    return r;
}
__device__ __forceinline__ float2 unpack2(ull v) {
    float a, b;
    asm("mov.b64 {%0,%1}, %2;" : "=f"(a), "=f"(b) : "l"(v));
    return make_float2(a, b);
}
__device__ __forceinline__ ull shflx_u64(ull v, int m) {
    uint lo = (uint)v, hi = (uint)(v >> 32);
    lo = __shfl_xor_sync(0xffffffffu, lo, m);
    hi = __shfl_xor_sync(0xffffffffu, hi, m);
    return ((ull)hi << 32) | (ull)lo;
}
__device__ __forceinline__ float tanh_fast(float x) {
    float r;
    asm("tanh.approx.f32 %0, %1;" : "=f"(r) : "f"(x));
    return r;
}
__device__ __forceinline__ float sig_fast(float x) {
    return fmaf(tanh_fast(0.5f * x), 0.5f, 0.5f);
}
__device__ __forceinline__ float logsigf_(float z) {
    if (z >= 0.0f) return -log1pf(expf(-z));
    return z - log1pf(expf(z));
}

// ---------------- clear + seed ----------------
__global__ void clear_kernel(const float* __restrict__ h0) {
    size_t i = (size_t)blockIdx.x * blockDim.x + threadIdx.x;
    if (i < HH) {
        g_p1[i] = packhf(0u, h0[i]);
        g_p2[i] = packhf(0u, h0[HH + i]);
    }
    const size_t N2 = (size_t)TT * HH / 2;
    ulonglong2* a = (ulonglong2*)(g_p1 + HH);
    ulonglong2* b = (ulonglong2*)(g_p2 + HH);
    ulonglong2 z; z.x = 0ull; z.y = 0ull;
    size_t stride = (size_t)gridDim.x * blockDim.x;
    for (size_t k = i; k < N2; k += stride) { a[k] = z; b[k] = z; }
}

// ---------------- persistent pipelined LSTM ----------------
// 129 blocks x 256 threads.
//   blocks [0,64):   layer 1 (8 outputs, one per warp)
//   blocks [64,128): layer 2 (8 outputs, one per warp)
//   block 128:       head + BCE loss
// Warp w owns output j0+w fully: 4 gate rows of W_ih AND W_hh.
// Lane l covers cols {c*128 + 4l .. +3} for chunks c=0..3 (conflict-free LDS.128).
__global__ void __launch_bounds__(256, 1) lstm_kernel(
    const float* __restrict__ x,
    const float* __restrict__ truth,
    const float* __restrict__ c0,
    const float* __restrict__ Wih0, const float* __restrict__ Whh0,
    const float* __restrict__ bih0, const float* __restrict__ bhh0,
    const float* __restrict__ Wih1, const float* __restrict__ Whh1,
    const float* __restrict__ bih1, const float* __restrict__ bhh1,
    const float* __restrict__ Whead, const float* __restrict__ bhead,
    float* __restrict__ out)
{
    const int b  = blockIdx.x;
    const int tt = threadIdx.x;

    // ================= HEAD + LOSS =================
    if (b == 128) {
        if (tt >= 32) return;
        float w0[16], w1[16];
#pragma unroll
        for (int i = 0; i < 16; i++) {
            w0[i] = Whead[tt * 16 + i];
            w1[i] = Whead[HH + tt * 16 + i];
        }
        const float bb0 = bhead[0], bb1 = bhead[1];
        double acc = 0.0;
        const ull* pe = g_p2 + HH + tt * 16;
        for (int t = 0; t < TT; t++, pe += HH) {
            const unsigned tgt = (unsigned)(t + 1);
            ull v[16];
            bool ok = false;
            while (!ok) {
                ok = true;
#pragma unroll
                for (int i = 0; i < 16; i++) {
                    v[i] = ld_rlx(pe + i);
                    ok &= (hi_u(v[i]) == tgt);
                }
            }
            float s0 = 0.f, s1 = 0.f;
#pragma unroll
            for (int i = 0; i < 16; i++) {
                float hv = lo_f(v[i]);
                s0 = fmaf(w0[i], hv, s0);
                s1 = fmaf(w1[i], hv, s1);
            }
#pragma unroll
            for (int m = 16; m >= 1; m >>= 1) {
                s0 += __shfl_xor_sync(0xffffffffu, s0, m);
                s1 += __shfl_xor_sync(0xffffffffu, s1, m);
            }
            if (tt == 0) {
                float z0 = s0 + bb0, z1 = s1 + bb1;
                float y0 = __ldg(truth + t * 2 + 0), y1 = __ldg(truth + t * 2 + 1);
                float t0 = y0 * fmaxf(logsigf_(z0), -100.0f)
                         + (1.0f - y0) * fmaxf(logsigf_(-z0), -100.0f);
                float t1 = y1 * fmaxf(logsigf_(z1), -100.0f)
                         + (1.0f - y1) * fmaxf(logsigf_(-z1), -100.0f);
                acc += (double)t0 + (double)t1;
            }
        }
        if (tt == 0) out[0] = (float)(-acc / (double)(TT * 2));
        return;
    }

    // ================= LSTM layer blocks =================
    const int role = b >> 6;
    const int j0   = (b & 63) * 8;
    const int w    = tt >> 5;      // warp = owned output
    const int l    = tt & 31;      // lane = 4-col slice per chunk
    const int j    = j0 + w;

    const float* WA = role ? Wih1 : Wih0;
    const float* WB = role ? Whh1 : Whh0;

    // register weights: [gate][chunk] -> 4 floats (2 ull) per matrix
    ulonglong2 wa[4][4], wb[4][4];
#pragma unroll
    for (int g = 0; g < 4; g++) {
        const size_t ro = (size_t)(g * HH + j) * HH;
#pragma unroll
        for (int cch = 0; cch < 4; cch++) {
            wa[g][cch] = *(const ulonglong2*)(WA + ro + cch * 128 + l * 4);
            wb[g][cch] = *(const ulonglong2*)(WB + ro + cch * 128 + l * 4);
        }
    }

    // per-lane copies of bias sums (identical across lanes)
    const float* bi = role ? bih1 : bih0;
    const float* bh = role ? bhh1 : bhh0;
    const float bs0 = bi[0 * HH + j] + bh[0 * HH + j];
    const float bs1 = bi[1 * HH + j] + bh[1 * HH + j];
    const float bs2 = bi[2 * HH + j] + bh[2 * HH + j];
    const float bs3 = bi[3 * HH + j] + bh[3 * HH + j];
    float c = c0[role * HH + j];

    __shared__ float vecs[2][2 * HH];   // double-buffered: [A(512) | B(512)]

    ull* myP = role ? g_p2 : g_p1;
    const ull* pA = g_p1 + HH + 2 * tt;        // layer-2 input slot t+1
    const ull* pB = myP + 2 * tt;              // own h[t-1] slot t
    const float2* px = (const float2*)x + tt;  // layer-1 input
    ull* myOut = myP + HH + j;                 // lane 0 stores

    for (int t = 0; t < TT; t++, pA += HH, pB += HH, px += HH / 2, myOut += HH) {
        float* vbuf = vecs[t & 1];
        const unsigned tgtA = (unsigned)(t + 1);
        const unsigned tgtB = (unsigned)t;
        float2 va, vbv;

        // ---- software-pipelined poll+load staging ----
        if (role == 0) {
            va = __ldg(px);
            ull b0 = ld_rlx(pB), b1 = ld_rlx(pB + 1);
            for (;;) {
                ull n0 = ld_rlx(pB), n1 = ld_rlx(pB + 1);   // next wave in flight
                if ((hi_u(b0) == tgtB) & (hi_u(b1) == tgtB)) break;
                b0 = n0; b1 = n1;
            }
            vbv = make_float2(lo_f(b0), lo_f(b1));
        } else {
            ull a0 = ld_rlx(pA), a1 = ld_rlx(pA + 1);
            ull b0 = ld_rlx(pB), b1 = ld_rlx(pB + 1);
            for (;;) {
                ull m0 = ld_rlx(pA), m1 = ld_rlx(pA + 1);
                ull n0 = ld_rlx(pB), n1 = ld_rlx(pB + 1);
                bool ok = (hi_u(a0) == tgtA) & (hi_u(a1) == tgtA)
                        & (hi_u(b0) == tgtB) & (hi_u(b1) == tgtB);
                if (ok) break;
                a0 = m0; a1 = m1; b0 = n0; b1 = n1;
            }
            va  = make_float2(lo_f(a0), lo_f(a1));
            vbv = make_float2(lo_f(b0), lo_f(b1));
        }
        ((float2*)vbuf)[tt] = va;
        ((float2*)(vbuf + HH))[tt] = vbv;
        __syncthreads();   // only barrier per step (double buffer kills the other hazard)

        // ---- vec chunks once, reused across all 4 gates ----
        ulonglong2 vA[4], vB[4];
#pragma unroll
        for (int cch = 0; cch < 4; cch++) {
            vA[cch] = *(const ulonglong2*)(vbuf + cch * 128 + l * 4);
            vB[cch] = *(const ulonglong2*)(vbuf + HH + cch * 128 + l * 4);
        }

        ull acc0 = 0ull, acc1 = 0ull, acc2 = 0ull, acc3 = 0ull;
#pragma unroll
        for (int cch = 0; cch < 4; cch++) {
            ffma2(acc0, wa[0][cch].x, vA[cch].x);
            ffma2(acc0, wa[0][cch].y, vA[cch].y);
            ffma2(acc1, wa[1][cch].x, vA[cch].x);
            ffma2(acc1, wa[1][cch].y, vA[cch].y);
            ffma2(acc2, wa[2][cch].x, vA[cch].x);
            ffma2(acc2, wa[2][cch].y, vA[cch].y);
            ffma2(acc3, wa[3][cch].x, vA[cch].x);
            ffma2(acc3, wa[3][cch].y, vA[cch].y);
            ffma2(acc0, wb[0][cch].x, vB[cch].x);
            ffma2(acc0, wb[0][cch].y, vB[cch].y);
            ffma2(acc1, wb[1][cch].x, vB[cch].x);
            ffma2(acc1, wb[1][cch].y, vB[cch].y);
            ffma2(acc2, wb[2][cch].x, vB[cch].x);
            ffma2(acc2, wb[2][cch].y, vB[cch].y);
            ffma2(acc3, wb[3][cch].x, vB[cch].x);
            ffma2(acc3, wb[3][cch].y, vB[cch].y);
        }

        // fold lo+hi, pack 4 gate partials into 2 packed words
        float2 u0 = unpack2(acc0), u1 = unpack2(acc1);
        float2 u2 = unpack2(acc2), u3 = unpack2(acc3);
        ull P0 = packf2(u0.x + u0.y, u1.x + u1.y);
        ull P1 = packf2(u2.x + u2.y, u3.x + u3.y);

        // 5-stage packed butterfly: every lane ends with all 4 gate sums
#pragma unroll
        for (int m = 1; m < 32; m <<= 1) {
            P0 = addf2(P0, shflx_u64(P0, m));
            P1 = addf2(P1, shflx_u64(P1, m));
        }
        float2 s01 = unpack2(P0), s23 = unpack2(P1);

        // ---- gates (all lanes redundantly; MUFU tanh) + store from lane 0 ----
        float ig = sig_fast(s01.x + bs0);
        float fg = sig_fast(s01.y + bs1);
        float gg = tanh_fast(s23.x + bs2);
        float og = sig_fast(s23.y + bs3);
        c = fg * c + ig * gg;
        float h = og * tanh_fast(c);
        if (l == 0) st_rlx(myOut, packhf((unsigned)(t + 1), h));
    }
}

extern "C" void kernel_launch(void* const* d_in, const int* in_sizes, int n_in,
                              void* d_out, int out_size) {
    const float* x     = (const float*)d_in[0];
    const float* truth = (const float*)d_in[1];
    const float* h0    = (const float*)d_in[2];
    const float* c0    = (const float*)d_in[3];
    const float* Wih0  = (const float*)d_in[4];
    const float* Whh0  = (const float*)d_in[5];
    const float* bih0  = (const float*)d_in[6];
    const float* bhh0  = (const float*)d_in[7];
    const float* Wih1  = (const float*)d_in[8];
    const float* Whh1  = (const float*)d_in[9];
    const float* bih1  = (const float*)d_in[10];
    const float* bhh1  = (const float*)d_in[11];
    const float* Whead = (const float*)d_in[12];
    const float* bhead = (const float*)d_in[13];
    float* out = (float*)d_out;

    clear_kernel<<<256, 1024>>>(h0);
    lstm_kernel<<<129, 256>>>(x, truth, c0,
                              Wih0, Whh0, bih0, bhh0,
                              Wih1, Whh1, bih1, bhh1,
                              Whead, bhead, out);
}

// round 5
// speedup vs baseline: 3.1591x; 3.1591x over previous
#include <cuda_runtime.h>
#include <math.h>

typedef unsigned long long ull;
typedef unsigned int uint;

#define TT 8192
#define HH 512

// ---------------- scratch: packed {flag(hi32), h_bits(lo32)} mailboxes ----------------
// slot k holds h^(k) (hidden after k steps); slot 0 = h0, flag k.
__device__ ull g_p1[(TT + 1) * HH];
__device__ ull g_p2[(TT + 1) * HH];

// ---------------- primitives ----------------
__device__ __forceinline__ ull ld_rlx(const ull* p) {
    ull v;
    asm volatile("ld.relaxed.gpu.global.u64 %0, [%1];" : "=l"(v) : "l"(p) : "memory");
    return v;
}
__device__ __forceinline__ void st_rlx(ull* p, ull v) {
    asm volatile("st.relaxed.gpu.global.u64 [%0], %1;" :: "l"(p), "l"(v) : "memory");
}
__device__ __forceinline__ ull packhf(unsigned flag, float h) {
    return ((ull)flag << 32) | (ull)__float_as_uint(h);
}
__device__ __forceinline__ float lo_f(ull v) { return __uint_as_float((unsigned)v); }
__device__ __forceinline__ unsigned hi_u(ull v) { return (unsigned)(v >> 32); }

__device__ __forceinline__ void ffma2(ull& acc, ull w, ull v) {
    asm("fma.rn.f32x2 %0, %1, %2, %0;" : "+l"(acc) : "l"(w), "l"(v));
}
__device__ __forceinline__ float2 unpack2(ull v) {
    float a, b;
    asm("mov.b64 {%0,%1}, %2;" : "=f"(a), "=f"(b) : "l"(v));
    return make_float2(a, b);
}
__device__ __forceinline__ float tanh_fast(float x) {
    float r;
    asm("tanh.approx.f32 %0, %1;" : "=f"(r) : "f"(x));
    return r;
}
__device__ __forceinline__ float sig_fast(float x) {
    return fmaf(tanh_fast(0.5f * x), 0.5f, 0.5f);
}
__device__ __forceinline__ float logsigf_(float z) {
    if (z >= 0.0f) return -log1pf(expf(-z));
    return z - log1pf(expf(z));
}
#define BAR_GRP(id) asm volatile("bar.sync %0, 128;" :: "r"(id) : "memory")

// ---------------- clear + seed ----------------
__global__ void clear_kernel(const float* __restrict__ h0) {
    size_t i = (size_t)blockIdx.x * blockDim.x + threadIdx.x;
    if (i < HH) {
        g_p1[i] = packhf(0u, h0[i]);
        g_p2[i] = packhf(0u, h0[HH + i]);
    }
    const size_t N2 = (size_t)TT * HH / 2;
    ulonglong2* a = (ulonglong2*)(g_p1 + HH);
    ulonglong2* b = (ulonglong2*)(g_p2 + HH);
    ulonglong2 z; z.x = 0ull; z.y = 0ull;
    size_t stride = (size_t)gridDim.x * blockDim.x;
    for (size_t k = i; k < N2; k += stride) { a[k] = z; b[k] = z; }
}

// ---------------- persistent pipelined LSTM ----------------
// 129 blocks x 256 threads.
//   blocks [0,64):   layer 1 (8 outputs each)
//   blocks [64,128): layer 2 (8 outputs each)
//   block 128:       head + BCE loss
// Early/late split:
//   threads [0,128):   EARLY group — vector available first
//                      (layer1: x[t]; layer2: own h2[t-1]) and its matrix rows
//   threads [128,256): LATE group — recurrence-critical vector
//                      (layer1: own h1[t-1]; layer2: h1[t]) and its matrix rows
// Within a group: u=tt&127; p=u>>3 (row pair of 32-row gate set); s=u&7 (64-col slice).
__global__ void __launch_bounds__(256, 1) lstm_kernel(
    const float* __restrict__ x,
    const float* __restrict__ truth,
    const float* __restrict__ c0,
    const float* __restrict__ Wih0, const float* __restrict__ Whh0,
    const float* __restrict__ bih0, const float* __restrict__ bhh0,
    const float* __restrict__ Wih1, const float* __restrict__ Whh1,
    const float* __restrict__ bih1, const float* __restrict__ bhh1,
    const float* __restrict__ Whead, const float* __restrict__ bhead,
    float* __restrict__ out)
{
    const int b  = blockIdx.x;
    const int tt = threadIdx.x;

    // ================= HEAD + LOSS =================
    if (b == 128) {
        if (tt >= 32) return;
        float w0[16], w1[16];
#pragma unroll
        for (int i = 0; i < 16; i++) {
            w0[i] = Whead[tt * 16 + i];
            w1[i] = Whead[HH + tt * 16 + i];
        }
        const float bb0 = bhead[0], bb1 = bhead[1];
        double acc = 0.0;
        const ull* pe = g_p2 + HH + tt * 16;
        for (int t = 0; t < TT; t++, pe += HH) {
            const unsigned tgt = (unsigned)(t + 1);
            ull v[16];
            bool ok = false;
            while (!ok) {
                ok = true;
#pragma unroll
                for (int i = 0; i < 16; i++) {
                    v[i] = ld_rlx(pe + i);
                    ok &= (hi_u(v[i]) == tgt);
                }
            }
            float s0 = 0.f, s1 = 0.f;
#pragma unroll
            for (int i = 0; i < 16; i++) {
                float hv = lo_f(v[i]);
                s0 = fmaf(w0[i], hv, s0);
                s1 = fmaf(w1[i], hv, s1);
            }
#pragma unroll
            for (int m = 16; m >= 1; m >>= 1) {
                s0 += __shfl_xor_sync(0xffffffffu, s0, m);
                s1 += __shfl_xor_sync(0xffffffffu, s1, m);
            }
            if (tt == 0) {
                float z0 = s0 + bb0, z1 = s1 + bb1;
                float y0 = __ldg(truth + t * 2 + 0), y1 = __ldg(truth + t * 2 + 1);
                float t0 = y0 * fmaxf(logsigf_(z0), -100.0f)
                         + (1.0f - y0) * fmaxf(logsigf_(-z0), -100.0f);
                float t1 = y1 * fmaxf(logsigf_(z1), -100.0f)
                         + (1.0f - y1) * fmaxf(logsigf_(-z1), -100.0f);
                acc += (double)t0 + (double)t1;
            }
        }
        if (tt == 0) out[0] = (float)(-acc / (double)(TT * 2));
        return;
    }

    // ================= LSTM layer blocks =================
    const int role = b >> 6;               // 0 = layer 1, 1 = layer 2
    const int j0   = (b & 63) * 8;
    const bool isL = (tt >= 128);          // late group?
    const int u    = tt & 127;
    const int p    = u >> 3;               // row pair 0..15
    const int s    = u & 7;                // 64-col slice
    const int rr0  = 2 * p;                // even row of the 32-row gate set
    const int gate = rr0 >> 3;
    const int jj   = rr0 & 7;

    // early matrix: layer1->W_ih, layer2->W_hh ; late matrix: the other one
    const float* Wih = role ? Wih1 : Wih0;
    const float* Whh = role ? Whh1 : Whh0;
    const float* WM  = isL ? (role ? Wih : Whh) : (role ? Whh : Wih);

    // register weights: 2 rows x 64-col slice, rotation-matched to LDS schedule
    ulonglong2 w0[16], w1[16];
    {
        const size_t ro = (size_t)(gate * HH + j0 + jj) * HH;
#pragma unroll
        for (int i = 0; i < 16; i++) {
            int col = s * 64 + 4 * ((i + s) & 15);
            w0[i] = *(const ulonglong2*)(WM + ro + col);
            w1[i] = *(const ulonglong2*)(WM + ro + HH + col);
        }
    }

    float bs0 = 0.f, bs1 = 0.f, bs2 = 0.f, bs3 = 0.f, c = 0.f;
    if (tt < 8) {
        const float* bi = role ? bih1 : bih0;
        const float* bh = role ? bhh1 : bhh0;
        bs0 = bi[0 * HH + j0 + tt] + bh[0 * HH + j0 + tt];
        bs1 = bi[1 * HH + j0 + tt] + bh[1 * HH + j0 + tt];
        bs2 = bi[2 * HH + j0 + tt] + bh[2 * HH + j0 + tt];
        bs3 = bi[3 * HH + j0 + tt] + bh[3 * HH + j0 + tt];
        c = c0[role * HH + j0 + tt];
    }

    __shared__ float vecs[2][2 * HH];   // parity-double-buffered: [E(512) | L(512)]
    __shared__ float gsum[2][64];       // parity-double-buffered gate partials

    ull* ownP = role ? g_p2 : g_p1;
    // EARLY source: layer1 -> x (no poll); layer2 -> own h2 slot t (tgt=t)
    const float4* px = (const float4*)x + u;         // +128/step
    const ull* pE = g_p2 + 4 * u;                    // +HH/step (role1 only)
    // LATE source: layer1 -> own h1 slot t (tgt=t); layer2 -> h1 slot t+1 (tgt=t+1)
    const ull* pL = role ? (g_p1 + HH + 4 * u) : (g_p1 + 4 * u);   // +HH/step
    ull* myOut = ownP + HH + j0 + tt;                // +HH/step (tt<8 stores)

    for (int t = 0; t < TT; t++, px += 128, pE += HH, pL += HH, myOut += HH) {
        float* vbuf = vecs[t & 1];
        float* gs   = gsum[t & 1];

        if (!isL) {
            // -------- EARLY group: stage + dot while late data is in flight --------
            float4 ve;
            if (role == 0) {
                ve = __ldg(px);
            } else {
                const unsigned tgt = (unsigned)t;
                ull v0, v1, v2, v3; bool ok = false;
                while (!ok) {
                    v0 = ld_rlx(pE);     v1 = ld_rlx(pE + 1);
                    v2 = ld_rlx(pE + 2); v3 = ld_rlx(pE + 3);
                    ok = (hi_u(v0) == tgt) & (hi_u(v1) == tgt)
                       & (hi_u(v2) == tgt) & (hi_u(v3) == tgt);
                }
                ve = make_float4(lo_f(v0), lo_f(v1), lo_f(v2), lo_f(v3));
            }
            ((float4*)vbuf)[u] = ve;
            BAR_GRP(1);

            const float* vb = vbuf + s * 64;
            ull a0 = 0ull, a1 = 0ull;
#pragma unroll
            for (int i = 0; i < 16; i++) {
                int idx = 4 * ((i + s) & 15);
                ulonglong2 v = *(const ulonglong2*)(vb + idx);
                ffma2(a0, w0[i].x, v.x);
                ffma2(a0, w0[i].y, v.y);
                ffma2(a1, w1[i].x, v.x);
                ffma2(a1, w1[i].y, v.y);
            }
            float2 f0 = unpack2(a0), f1 = unpack2(a1);
            float s0 = f0.x + f0.y, s1 = f1.x + f1.y;
            s0 += __shfl_xor_sync(0xffffffffu, s0, 1);
            s1 += __shfl_xor_sync(0xffffffffu, s1, 1);
            s0 += __shfl_xor_sync(0xffffffffu, s0, 2);
            s1 += __shfl_xor_sync(0xffffffffu, s1, 2);
            s0 += __shfl_xor_sync(0xffffffffu, s0, 4);
            s1 += __shfl_xor_sync(0xffffffffu, s1, 4);
            if (s == 0) { gs[rr0] = s0; gs[rr0 + 1] = s1; }
        } else {
            // -------- LATE group: recurrence-critical path --------
            const unsigned tgt = (unsigned)(role ? t + 1 : t);
            ull v0, v1, v2, v3; bool ok = false;
            while (!ok) {
                v0 = ld_rlx(pL);     v1 = ld_rlx(pL + 1);
                v2 = ld_rlx(pL + 2); v3 = ld_rlx(pL + 3);
                ok = (hi_u(v0) == tgt) & (hi_u(v1) == tgt)
                   & (hi_u(v2) == tgt) & (hi_u(v3) == tgt);
            }
            ((float4*)(vbuf + HH))[u] =
                make_float4(lo_f(v0), lo_f(v1), lo_f(v2), lo_f(v3));
            BAR_GRP(2);

            const float* vb = vbuf + HH + s * 64;
            ull a0 = 0ull, a1 = 0ull;
#pragma unroll
            for (int i = 0; i < 16; i++) {
                int idx = 4 * ((i + s) & 15);
                ulonglong2 v = *(const ulonglong2*)(vb + idx);
                ffma2(a0, w0[i].x, v.x);
                ffma2(a0, w0[i].y, v.y);
                ffma2(a1, w1[i].x, v.x);
                ffma2(a1, w1[i].y, v.y);
            }
            float2 f0 = unpack2(a0), f1 = unpack2(a1);
            float s0 = f0.x + f0.y, s1 = f1.x + f1.y;
            s0 += __shfl_xor_sync(0xffffffffu, s0, 1);
            s1 += __shfl_xor_sync(0xffffffffu, s1, 1);
            s0 += __shfl_xor_sync(0xffffffffu, s0, 2);
            s1 += __shfl_xor_sync(0xffffffffu, s1, 2);
            s0 += __shfl_xor_sync(0xffffffffu, s0, 4);
            s1 += __shfl_xor_sync(0xffffffffu, s1, 4);
            if (s == 0) { gs[32 + rr0] = s0; gs[32 + rr0 + 1] = s1; }
        }

        __syncthreads();   // combine point (early group is already parked here)

        if (tt < 8) {
            float p0 = gs[0 * 8 + tt] + gs[32 + 0 * 8 + tt] + bs0;
            float p1 = gs[1 * 8 + tt] + gs[32 + 1 * 8 + tt] + bs1;
            float p2 = gs[2 * 8 + tt] + gs[32 + 2 * 8 + tt] + bs2;
            float p3 = gs[3 * 8 + tt] + gs[32 + 3 * 8 + tt] + bs3;
            float ig = sig_fast(p0);
            float fg = sig_fast(p1);
            float gg = tanh_fast(p2);
            float og = sig_fast(p3);
            c = fg * c + ig * gg;
            float h = og * tanh_fast(c);
            st_rlx(myOut, packhf((unsigned)(t + 1), h));
        }
    }
}

extern "C" void kernel_launch(void* const* d_in, const int* in_sizes, int n_in,
                              void* d_out, int out_size) {
    const float* x     = (const float*)d_in[0];
    const float* truth = (const float*)d_in[1];
    const float* h0    = (const float*)d_in[2];
    const float* c0    = (const float*)d_in[3];
    const float* Wih0  = (const float*)d_in[4];
    const float* Whh0  = (const float*)d_in[5];
    const float* bih0  = (const float*)d_in[6];
    const float* bhh0  = (const float*)d_in[7];
    const float* Wih1  = (const float*)d_in[8];
    const float* Whh1  = (const float*)d_in[9];
    const float* bih1  = (const float*)d_in[10];
    const float* bhh1  = (const float*)d_in[11];
    const float* Whead = (const float*)d_in[12];
    const float* bhead = (const float*)d_in[13];
    float* out = (float*)d_out;

    clear_kernel<<<256, 1024>>>(h0);
    lstm_kernel<<<129, 256>>>(x, truth, c0,
                              Wih0, Whh0, bih0, bhh0,
                              Wih1, Whh1, bih1, bhh1,
                              Whead, bhead, out);
}